// round 16
// baseline (speedup 1.0000x reference)
#include <cuda_runtime.h>
#include <cuda_bf16.h>
#include <math.h>
#include <stdint.h>

#define HW 16384
#define NB 32

// ---------------- scratch (static device globals) ----------------
__device__ __align__(16) __nv_bfloat16 g_fh[(size_t)4096 * 8192];
__device__ __align__(16) __nv_bfloat16 g_fl[(size_t)4096 * 8192];
__device__ __align__(16) __nv_bfloat16 g_wh[10 * 4096];   // mats 0-7 experts, 8-9 shared; [o][c]
__device__ __align__(16) __nv_bfloat16 g_wl[10 * 4096];
__device__ __align__(16) __nv_bfloat16 g_fwh[4096];       // fe_w [o][c]
__device__ __align__(16) __nv_bfloat16 g_fwl[4096];
__device__ float g_gf[NB * 64];
__device__ int   g_tidx[NB * 2];
__device__ float g_tw[NB * 2];

__device__ __forceinline__ float rcp_approx(float v) {
    float r; asm("rcp.approx.f32 %0, %1;" : "=f"(r) : "f"(v)); return r;
}
__device__ __forceinline__ float ex2_approx(float v) {
    float r; asm("ex2.approx.f32 %0, %1;" : "=f"(r) : "f"(v)); return r;
}
// Branchless gelu: erf via Abramowitz-Stegun 7.1.26 (|err| <= 1.5e-7)
__device__ __forceinline__ float gelu_f(float x) {
    float a = fabsf(x) * 0.7071067811865476f;
    float t = rcp_approx(fmaf(0.3275911f, a, 1.0f));
    float ex = ex2_approx((-1.4426950408889634f * a) * a);
    float p = fmaf(1.061405429f, t, -1.453152027f);
    p = fmaf(p, t, 1.421413741f);
    p = fmaf(p, t, -0.284496736f);
    p = fmaf(p, t, 0.254829592f);
    float e = fmaf(-p * t, ex, 1.0f);
    float er = copysignf(e, x);
    float hx = 0.5f * x;
    return fmaf(hx, er, hx);
}
__device__ __forceinline__ void bsplit(float v, __nv_bfloat16& h, __nv_bfloat16& l) {
    h = __float2bfloat16(v);
    l = __float2bfloat16(v - __bfloat162float(h));
}
__device__ __forceinline__ uint32_t smem_u32(const void* p) {
    uint32_t a;
    asm("{ .reg .u64 t; cvta.to.shared.u64 t, %1; cvt.u32.u64 %0, t; }" : "=r"(a) : "l"(p));
    return a;
}
__device__ __forceinline__ void ldsm4(uint32_t* r, uint32_t a) {
    asm volatile("ldmatrix.sync.aligned.m8n8.x4.shared.b16 {%0,%1,%2,%3}, [%4];"
                 : "=r"(r[0]), "=r"(r[1]), "=r"(r[2]), "=r"(r[3]) : "r"(a));
}
__device__ __forceinline__ void ldsm4t(uint32_t* r, uint32_t a) {
    asm volatile("ldmatrix.sync.aligned.m8n8.x4.trans.shared.b16 {%0,%1,%2,%3}, [%4];"
                 : "=r"(r[0]), "=r"(r[1]), "=r"(r[2]), "=r"(r[3]) : "r"(a));
}
__device__ __forceinline__ void mma16816(float* d, const uint32_t* a, const uint32_t* b) {
    asm volatile(
        "mma.sync.aligned.m16n8k16.row.col.f32.bf16.bf16.f32 "
        "{%0,%1,%2,%3}, {%4,%5,%6,%7}, {%8,%9}, {%0,%1,%2,%3};"
        : "+f"(d[0]), "+f"(d[1]), "+f"(d[2]), "+f"(d[3])
        : "r"(a[0]), "r"(a[1]), "r"(a[2]), "r"(a[3]), "r"(b[0]), "r"(b[1]));
}
__device__ __forceinline__ uint32_t pack_bf2(__nv_bfloat16 lo, __nv_bfloat16 hi) {
    return ((uint32_t)__bfloat16_as_ushort(hi) << 16) | __bfloat16_as_ushort(lo);
}

#define AS_B 272   // A smem row stride bytes: [k=c rows][m=p cols], 136 bf16
#define BS_B 144   // B smem row stride bytes: [n rows][k cols], 72 bf16

// ---------------- prep: zero gf, bf16-split all weights ----------------
__global__ void prep_kernel(const float* __restrict__ fe_w,
                            const float* __restrict__ s_w,
                            const float* __restrict__ e_w) {
    int gt = blockIdx.x * blockDim.x + threadIdx.x;
    int stride = gridDim.x * blockDim.x;
    for (int i = gt; i < NB * 64; i += stride) g_gf[i] = 0.0f;
    for (int i = gt; i < 4096; i += stride) {
        __nv_bfloat16 h, l; bsplit(fe_w[i], h, l);
        g_fwh[i] = h; g_fwl[i] = l;
    }
    for (int i = gt; i < 10 * 4096; i += stride) {
        int m = i >> 12, r = i & 4095;
        float v = (m < 8) ? e_w[i] : s_w[(m - 8) * 4096 + r];
        __nv_bfloat16 h, l; bsplit(v, h, l);
        g_wh[i] = h; g_wl[i] = l;
    }
}

// ---------------- kernel 1: features + SHARED experts (fused) ----------------
// Phase 1: features = gelu(x @ fe_w^T + fe_b)  (M=128, N=64, K=64, 3-pass)
// Phase 2: shared  = 0.5*gelu(feat @ s0^T + b0) + 0.5*gelu(feat @ s1^T + b1)
//          using the staged bf16 features as the A operand (same layout).
#define F_AH 0
#define F_AL 17408
#define F_BH 34816
#define F_BL 44032
#define F_SB 53248     // + q*18432 (hi), +9216 (lo), q in {0,1}: shared mats
#define F_SMEM 90112
__global__ __launch_bounds__(256, 2) void feat_mma(const float* __restrict__ x,
                                                   const float* __restrict__ fe_b,
                                                   const float* __restrict__ s_b,
                                                   float* __restrict__ out) {
    extern __shared__ char sm[];
    uint32_t sb = smem_u32(sm);
    int tid = threadIdx.x, wid = tid >> 5, lid = tid & 31;
    int b = blockIdx.x >> 7, t = blockIdx.x & 127;

    // stage A: x [c][p] (read-once, streaming) -> split bf16 smem [c][p]
    const float* xb = x + (size_t)b * 64 * HW + (size_t)t * 128;
    #pragma unroll
    for (int it = 0; it < 8; it++) {
        int idx = tid + it * 256;
        int p4 = idx & 31, c = idx >> 5;
        float4 v = __ldcs((const float4*)(xb + (size_t)c * HW + p4 * 4));
        __nv_bfloat16 h0, l0, h1, l1, h2, l2, h3, l3;
        bsplit(v.x, h0, l0); bsplit(v.y, h1, l1);
        bsplit(v.z, h2, l2); bsplit(v.w, h3, l3);
        *(uint2*)(sm + F_AH + c * AS_B + p4 * 8) =
            make_uint2(pack_bf2(h0, h1), pack_bf2(h2, h3));
        *(uint2*)(sm + F_AL + c * AS_B + p4 * 8) =
            make_uint2(pack_bf2(l0, l1), pack_bf2(l2, l3));
    }
    // stage B: fe_w planes + the two shared-expert weight mats (8, 9)
    for (int i = tid; i < 512; i += 256) {
        int o = i >> 3, ch = i & 7;
        *(uint4*)(sm + F_BH + o * BS_B + ch * 16) = ((const uint4*)g_fwh)[i];
        *(uint4*)(sm + F_BL + o * BS_B + ch * 16) = ((const uint4*)g_fwl)[i];
    }
    #pragma unroll
    for (int q = 0; q < 2; q++) {
        const uint4* bh = (const uint4*)(g_wh + (8 + q) * 4096);
        const uint4* bl = (const uint4*)(g_wl + (8 + q) * 4096);
        uint32_t bo = F_SB + q * 18432;
        for (int i = tid; i < 512; i += 256) {
            int o = i >> 3, ch = i & 7;
            *(uint4*)(sm + bo + o * BS_B + ch * 16) = bh[i];
            *(uint4*)(sm + bo + 9216 + o * BS_B + ch * 16) = bl[i];
        }
    }
    __syncthreads();

    int wm = wid & 3, wn = wid >> 2;      // 4 x 2 warp grid, tile 32x32
    int m0 = wm * 32, n0 = wn * 32;

    int asel = lid >> 3, akr = lid & 7;
    uint32_t aRow = (uint32_t)(((asel >> 1) * 8 + akr) * AS_B);
    uint32_t aCol = (uint32_t)((m0 + (asel & 1) * 8) * 2);
    int bsel = lid >> 3;
    uint32_t bRow = (uint32_t)(((bsel >> 1) * 8 + (lid & 7)) * BS_B);
    uint32_t bCol = (uint32_t)((bsel & 1) * 16);

    float acc[2][4][4];
    #pragma unroll
    for (int i = 0; i < 2; i++)
        #pragma unroll
        for (int j = 0; j < 4; j++)
            #pragma unroll
            for (int k = 0; k < 4; k++) acc[i][j][k] = 0.0f;

    // ---- phase 1: features ----
    {
        uint32_t afh[4][2][4];
        #pragma unroll
        for (int kk = 0; kk < 4; kk++) {
            uint32_t Ab = sb + F_AH + aRow + aCol + kk * 16 * AS_B;
            ldsm4t(afh[kk][0], Ab);
            ldsm4t(afh[kk][1], Ab + 32);
        }
        #pragma unroll
        for (int pb = 0; pb < 2; pb++) {
            uint32_t Bb = sb + (pb ? F_BL : F_BH) + bRow + bCol;
            #pragma unroll
            for (int kk = 0; kk < 4; kk++) {
                uint32_t bq0[4], bq1[4];
                ldsm4(bq0, Bb + n0 * BS_B + kk * 32);
                ldsm4(bq1, Bb + (n0 + 16) * BS_B + kk * 32);
                #pragma unroll
                for (int mt = 0; mt < 2; mt++) {
                    mma16816(acc[mt][0], afh[kk][mt], &bq0[0]);
                    mma16816(acc[mt][1], afh[kk][mt], &bq0[2]);
                    mma16816(acc[mt][2], afh[kk][mt], &bq1[0]);
                    mma16816(acc[mt][3], afh[kk][mt], &bq1[2]);
                }
            }
        }
        {
            uint32_t Bb = sb + F_BH + bRow + bCol;
            #pragma unroll
            for (int kk = 0; kk < 4; kk++) {
                uint32_t afl[2][4], bq0[4], bq1[4];
                uint32_t Abl = sb + F_AL + aRow + aCol + kk * 16 * AS_B;
                ldsm4t(afl[0], Abl);
                ldsm4t(afl[1], Abl + 32);
                ldsm4(bq0, Bb + n0 * BS_B + kk * 32);
                ldsm4(bq1, Bb + (n0 + 16) * BS_B + kk * 32);
                #pragma unroll
                for (int mt = 0; mt < 2; mt++) {
                    mma16816(acc[mt][0], afl[mt], &bq0[0]);
                    mma16816(acc[mt][1], afl[mt], &bq0[2]);
                    mma16816(acc[mt][2], afl[mt], &bq1[0]);
                    mma16816(acc[mt][3], afl[mt], &bq1[2]);
                }
            }
        }
    }
    __syncthreads();   // done reading x-A; reuse A region as feature staging [c][p]

    int r0 = lid >> 2, cq = (lid & 3) * 2;
    {
        float colsum[8];
        #pragma unroll
        for (int j = 0; j < 8; j++) colsum[j] = 0.0f;

        #pragma unroll
        for (int mt = 0; mt < 2; mt++)
            #pragma unroll
            for (int nt = 0; nt < 4; nt++) {
                int c0 = n0 + nt * 8 + cq;
                float bi0 = __ldg(&fe_b[c0]), bi1 = __ldg(&fe_b[c0 + 1]);
                #pragma unroll
                for (int hr = 0; hr < 2; hr++) {
                    int p = m0 + mt * 16 + r0 + hr * 8;
                    float v0 = gelu_f(acc[mt][nt][hr * 2 + 0] + bi0);
                    float v1 = gelu_f(acc[mt][nt][hr * 2 + 1] + bi1);
                    colsum[nt * 2 + 0] += v0;
                    colsum[nt * 2 + 1] += v1;
                    __nv_bfloat16 h, l;
                    bsplit(v0, h, l);
                    *(__nv_bfloat16*)(sm + F_AH + c0 * AS_B + p * 2) = h;
                    *(__nv_bfloat16*)(sm + F_AL + c0 * AS_B + p * 2) = l;
                    bsplit(v1, h, l);
                    *(__nv_bfloat16*)(sm + F_AH + (c0 + 1) * AS_B + p * 2) = h;
                    *(__nv_bfloat16*)(sm + F_AL + (c0 + 1) * AS_B + p * 2) = l;
                }
            }
        #pragma unroll
        for (int off = 16; off >= 4; off >>= 1)
            #pragma unroll
            for (int j = 0; j < 8; j++)
                colsum[j] += __shfl_down_sync(0xffffffffu, colsum[j], off);
        if (lid < 4) {
            #pragma unroll
            for (int nt = 0; nt < 4; nt++) {
                atomicAdd(&g_gf[b * 64 + n0 + nt * 8 + cq + 0], colsum[nt * 2 + 0]);
                atomicAdd(&g_gf[b * 64 + n0 + nt * 8 + cq + 1], colsum[nt * 2 + 1]);
            }
        }
    }
    __syncthreads();

    // writeback staging -> gmem planes [c][128] (routed experts still need them)
    {
        uint4* dh = (uint4*)(g_fh + (size_t)blockIdx.x * 8192);
        uint4* dl = (uint4*)(g_fl + (size_t)blockIdx.x * 8192);
        for (int i = tid; i < 1024; i += 256) {
            int row = i >> 4, ch = i & 15;
            dh[i] = *(const uint4*)(sm + F_AH + row * AS_B + ch * 16);
            dl[i] = *(const uint4*)(sm + F_AL + row * AS_B + ch * 16);
        }
    }

    // ---- phase 2: shared experts from staged features ----
    float comb[2][4][4];
    #pragma unroll
    for (int i = 0; i < 2; i++)
        #pragma unroll
        for (int j = 0; j < 4; j++)
            #pragma unroll
            for (int k = 0; k < 4; k++) comb[i][j][k] = 0.0f;

    uint32_t afh2[4][2][4];
    #pragma unroll
    for (int kk = 0; kk < 4; kk++) {
        uint32_t Ab = sb + F_AH + aRow + aCol + kk * 16 * AS_B;
        ldsm4t(afh2[kk][0], Ab);
        ldsm4t(afh2[kk][1], Ab + 32);
    }

    #pragma unroll
    for (int q = 0; q < 2; q++) {
        #pragma unroll
        for (int i = 0; i < 2; i++)
            #pragma unroll
            for (int j = 0; j < 4; j++)
                #pragma unroll
                for (int k = 0; k < 4; k++) acc[i][j][k] = 0.0f;

        uint32_t Bbase = sb + F_SB + q * 18432 + bRow + bCol;
        #pragma unroll
        for (int pb = 0; pb < 2; pb++) {
            uint32_t Bb = Bbase + (pb ? 9216u : 0u);
            #pragma unroll
            for (int kk = 0; kk < 4; kk++) {
                uint32_t bq0[4], bq1[4];
                ldsm4(bq0, Bb + n0 * BS_B + kk * 32);
                ldsm4(bq1, Bb + (n0 + 16) * BS_B + kk * 32);
                #pragma unroll
                for (int mt = 0; mt < 2; mt++) {
                    mma16816(acc[mt][0], afh2[kk][mt], &bq0[0]);
                    mma16816(acc[mt][1], afh2[kk][mt], &bq0[2]);
                    mma16816(acc[mt][2], afh2[kk][mt], &bq1[0]);
                    mma16816(acc[mt][3], afh2[kk][mt], &bq1[2]);
                }
            }
        }
        #pragma unroll
        for (int kk = 0; kk < 4; kk++) {
            uint32_t afl[2][4], bq0[4], bq1[4];
            uint32_t Abl = sb + F_AL + aRow + aCol + kk * 16 * AS_B;
            ldsm4t(afl[0], Abl);
            ldsm4t(afl[1], Abl + 32);
            ldsm4(bq0, Bbase + n0 * BS_B + kk * 32);
            ldsm4(bq1, Bbase + (n0 + 16) * BS_B + kk * 32);
            #pragma unroll
            for (int mt = 0; mt < 2; mt++) {
                mma16816(acc[mt][0], afl[mt], &bq0[0]);
                mma16816(acc[mt][1], afl[mt], &bq0[2]);
                mma16816(acc[mt][2], afl[mt], &bq1[0]);
                mma16816(acc[mt][3], afl[mt], &bq1[2]);
            }
        }
        #pragma unroll
        for (int nt = 0; nt < 4; nt++) {
            int c0 = n0 + nt * 8 + cq;
            float bi0 = __ldg(&s_b[q * 64 + c0]), bi1 = __ldg(&s_b[q * 64 + c0 + 1]);
            #pragma unroll
            for (int mt = 0; mt < 2; mt++)
                #pragma unroll
                for (int hr = 0; hr < 2; hr++) {
                    comb[mt][nt][hr * 2 + 0] += 0.5f * gelu_f(acc[mt][nt][hr * 2 + 0] + bi0);
                    comb[mt][nt][hr * 2 + 1] += 0.5f * gelu_f(acc[mt][nt][hr * 2 + 1] + bi1);
                }
        }
    }

    // write shared partial to out (re-read by out_mma -> default caching)
    float* ob = out + (size_t)b * 64 * HW + (size_t)t * 128;
    #pragma unroll
    for (int nt = 0; nt < 4; nt++) {
        int c0 = n0 + nt * 8 + cq;
        float* row0 = ob + (size_t)c0 * HW;
        float* row1 = ob + (size_t)(c0 + 1) * HW;
        #pragma unroll
        for (int mt = 0; mt < 2; mt++)
            #pragma unroll
            for (int hr = 0; hr < 2; hr++) {
                int p = m0 + mt * 16 + r0 + hr * 8;
                row0[p] = comb[mt][nt][hr * 2 + 0];
                row1[p] = comb[mt][nt][hr * 2 + 1];
            }
    }
}

// ---------------- kernel 2: gating MLP (single block, fp32) ----------------
__global__ __launch_bounds__(256) void gate_kernel(
        const float* __restrict__ g1_w, const float* __restrict__ g1_b,
        const float* __restrict__ bn1_g, const float* __restrict__ bn1_b,
        const float* __restrict__ ca1_w, const float* __restrict__ ca1_b,
        const float* __restrict__ ca2_w, const float* __restrict__ ca2_b,
        const float* __restrict__ g2_w, const float* __restrict__ g2_b,
        const float* __restrict__ bn2_g, const float* __restrict__ bn2_b,
        const float* __restrict__ g3_w, const float* __restrict__ g3_b) {
    __shared__ float gf[32][64];
    __shared__ float h1[32][128];
    __shared__ float a1[32][8];
    __shared__ float hh[32][64];
    __shared__ float sc[32][8];

    int tid = threadIdx.x;
    const float bnscale = rsqrtf(1.0f + 1e-5f);
    const float inv_hw = 1.0f / 16384.0f;

    for (int i = tid; i < 2048; i += 256) gf[i >> 6][i & 63] = g_gf[i] * inv_hw;
    __syncthreads();

    for (int i = tid; i < 4096; i += 256) {
        int b = i >> 7, j = i & 127;
        float s = g1_b[j];
        #pragma unroll 8
        for (int h = 0; h < 64; h++) s += gf[b][h] * g1_w[j * 64 + h];
        s = s * (bn1_g[j] * bnscale) + bn1_b[j];
        h1[b][j] = gelu_f(s);
    }
    __syncthreads();
    {
        int b = tid >> 3, i = tid & 7;
        float s = ca1_b[i];
        #pragma unroll 8
        for (int h = 0; h < 128; h++) s += h1[b][h] * ca1_w[i * 128 + h];
        a1[b][i] = gelu_f(s);
    }
    __syncthreads();
    for (int i = tid; i < 4096; i += 256) {
        int b = i >> 7, j = i & 127;
        float s = ca2_b[j];
        #pragma unroll
        for (int k = 0; k < 8; k++) s += a1[b][k] * ca2_w[j * 8 + k];
        h1[b][j] *= 1.0f / (1.0f + expf(-2.0f * s));
    }
    __syncthreads();
    for (int i = tid; i < 2048; i += 256) {
        int b = i >> 6, j = i & 63;
        float s = g2_b[j];
        #pragma unroll 8
        for (int h = 0; h < 128; h++) s += h1[b][h] * g2_w[j * 128 + h];
        s = s * (bn2_g[j] * bnscale) + bn2_b[j];
        hh[b][j] = gelu_f(s);
    }
    __syncthreads();
    {
        int b = tid >> 3, e = tid & 7;
        float s = g3_b[e];
        #pragma unroll 8
        for (int h = 0; h < 64; h++) s += hh[b][h] * g3_w[e * 64 + h];
        sc[b][e] = s;
    }
    __syncthreads();
    if (tid < 32) {
        int b = tid;
        float v1 = -INFINITY; int i1 = 0;
        for (int e = 0; e < 8; e++) { float v = sc[b][e]; if (v > v1) { v1 = v; i1 = e; } }
        float v2 = -INFINITY; int i2 = 0;
        for (int e = 0; e < 8; e++) {
            if (e == i1) continue;
            float v = sc[b][e]; if (v > v2) { v2 = v; i2 = e; }
        }
        float w1 = 1.0f / (1.0f + expf((v2 - v1) * 0.5f));
        g_tidx[b * 2 + 0] = i1; g_tidx[b * 2 + 1] = i2;
        g_tw[b * 2 + 0] = w1;  g_tw[b * 2 + 1] = 1.0f - w1;
    }
}

// ---------------- kernel 3: ROUTED experts only (2 mats), RMW onto shared partial ----------------
// Reverse tile order (L2 reuse of freshest planes); streaming final stores.
#define O_AH 0
#define O_AL 17408
#define O_B  34816     // + q*18432 (hi), +9216 (lo), q in {0,1}
#define O_BIAS 71680   // 128 floats
#define O_SMEM 72192
__global__ __launch_bounds__(256, 2) void out_mma(const float* __restrict__ e_b,
                                                  float* __restrict__ out) {
    extern __shared__ char sm[];
    uint32_t sb = smem_u32(sm);
    int tid = threadIdx.x, wid = tid >> 5, lid = tid & 31;
    int gt = 4095 - blockIdx.x;           // reverse tile order for L2 reuse
    int b = gt >> 7, t = gt & 127;

    int e0 = g_tidx[2 * b], e1 = g_tidx[2 * b + 1];
    float cfa[2] = {g_tw[2 * b], g_tw[2 * b + 1]};

    // stage A: pre-split feature planes
    {
        const uint4* ah = (const uint4*)(g_fh + (size_t)gt * 8192);
        const uint4* al = (const uint4*)(g_fl + (size_t)gt * 8192);
        for (int i = tid; i < 1024; i += 256) {
            int row = i >> 4, ch = i & 15;
            *(uint4*)(sm + O_AH + row * AS_B + ch * 16) = ah[i];
            *(uint4*)(sm + O_AL + row * AS_B + ch * 16) = al[i];
        }
    }
    // stage B: the 2 routed mats
    {
        int mats[2] = {e0, e1};
        #pragma unroll
        for (int q = 0; q < 2; q++) {
            const uint4* bh = (const uint4*)(g_wh + mats[q] * 4096);
            const uint4* bl = (const uint4*)(g_wl + mats[q] * 4096);
            uint32_t bo = O_B + q * 18432;
            for (int i = tid; i < 512; i += 256) {
                int o = i >> 3, ch = i & 7;
                *(uint4*)(sm + bo + o * BS_B + ch * 16) = bh[i];
                *(uint4*)(sm + bo + 9216 + o * BS_B + ch * 16) = bl[i];
            }
        }
        if (tid < 128) {
            int m = tid >> 6, o = tid & 63;
            *(float*)(sm + O_BIAS + tid * 4) = e_b[((m == 0) ? e0 : e1) * 64 + o];
        }
    }
    __syncthreads();

    int wm = wid & 3, wn = wid >> 2;
    int m0 = wm * 32, n0 = wn * 32;

    int asel = lid >> 3, akr = lid & 7;
    uint32_t aRow = (uint32_t)(((asel >> 1) * 8 + akr) * AS_B);
    uint32_t aCol = (uint32_t)((m0 + (asel & 1) * 8) * 2);
    int bsel = lid >> 3;
    uint32_t bRow = (uint32_t)(((bsel >> 1) * 8 + (lid & 7)) * BS_B);
    uint32_t bCol = (uint32_t)((bsel & 1) * 16);

    int rr = lid >> 2, cq = (lid & 3) * 2;
    const float* bias = (const float*)(sm + O_BIAS);

    uint32_t afh[4][2][4];
    #pragma unroll
    for (int kk = 0; kk < 4; kk++) {
        uint32_t Ab = sb + O_AH + aRow + aCol + kk * 16 * AS_B;
        ldsm4t(afh[kk][0], Ab);
        ldsm4t(afh[kk][1], Ab + 32);
    }

    float comb[2][4][4];
    #pragma unroll
    for (int i = 0; i < 2; i++)
        #pragma unroll
        for (int j = 0; j < 4; j++)
            #pragma unroll
            for (int k = 0; k < 4; k++) comb[i][j][k] = 0.0f;

    #pragma unroll
    for (int q = 0; q < 2; q++) {
        float acc[2][4][4];
        #pragma unroll
        for (int i = 0; i < 2; i++)
            #pragma unroll
            for (int j = 0; j < 4; j++)
                #pragma unroll
                for (int k = 0; k < 4; k++) acc[i][j][k] = 0.0f;

        uint32_t Bbase = sb + O_B + q * 18432 + bRow + bCol;
        #pragma unroll
        for (int pb = 0; pb < 2; pb++) {
            uint32_t Bb = Bbase + (pb ? 9216u : 0u);
            #pragma unroll
            for (int kk = 0; kk < 4; kk++) {
                uint32_t bq0[4], bq1[4];
                ldsm4(bq0, Bb + n0 * BS_B + kk * 32);
                ldsm4(bq1, Bb + (n0 + 16) * BS_B + kk * 32);
                #pragma unroll
                for (int mt = 0; mt < 2; mt++) {
                    mma16816(acc[mt][0], afh[kk][mt], &bq0[0]);
                    mma16816(acc[mt][1], afh[kk][mt], &bq0[2]);
                    mma16816(acc[mt][2], afh[kk][mt], &bq1[0]);
                    mma16816(acc[mt][3], afh[kk][mt], &bq1[2]);
                }
            }
        }
        #pragma unroll
        for (int kk = 0; kk < 4; kk++) {
            uint32_t afl[2][4], bq0[4], bq1[4];
            uint32_t Abl = sb + O_AL + aRow + aCol + kk * 16 * AS_B;
            ldsm4t(afl[0], Abl);
            ldsm4t(afl[1], Abl + 32);
            ldsm4(bq0, Bbase + n0 * BS_B + kk * 32);
            ldsm4(bq1, Bbase + (n0 + 16) * BS_B + kk * 32);
            #pragma unroll
            for (int mt = 0; mt < 2; mt++) {
                mma16816(acc[mt][0], afl[mt], &bq0[0]);
                mma16816(acc[mt][1], afl[mt], &bq0[2]);
                mma16816(acc[mt][2], afl[mt], &bq1[0]);
                mma16816(acc[mt][3], afl[mt], &bq1[2]);
            }
        }
        float cf = cfa[q];
        #pragma unroll
        for (int nt = 0; nt < 4; nt++) {
            int c0 = n0 + nt * 8 + cq;
            float bi0 = bias[q * 64 + c0], bi1 = bias[q * 64 + c0 + 1];
            #pragma unroll
            for (int mt = 0; mt < 2; mt++)
                #pragma unroll
                for (int hr = 0; hr < 2; hr++) {
                    comb[mt][nt][hr * 2 + 0] += cf * gelu_f(acc[mt][nt][hr * 2 + 0] + bi0);
                    comb[mt][nt][hr * 2 + 1] += cf * gelu_f(acc[mt][nt][hr * 2 + 1] + bi1);
                }
        }
    }

    // RMW: final = shared partial (written by feat) + routed; streaming final store
    float* ob = out + (size_t)b * 64 * HW + (size_t)t * 128;
    #pragma unroll
    for (int nt = 0; nt < 4; nt++) {
        int c0 = n0 + nt * 8 + cq;
        float* row0 = ob + (size_t)c0 * HW;
        float* row1 = ob + (size_t)(c0 + 1) * HW;
        #pragma unroll
        for (int mt = 0; mt < 2; mt++)
            #pragma unroll
            for (int hr = 0; hr < 2; hr++) {
                int p = m0 + mt * 16 + rr + hr * 8;
                __stcs(&row0[p], row0[p] + comb[mt][nt][hr * 2 + 0]);
                __stcs(&row1[p], row1[p] + comb[mt][nt][hr * 2 + 1]);
            }
    }
}

// ---------------- launch ----------------
extern "C" void kernel_launch(void* const* d_in, const int* in_sizes, int n_in,
                              void* d_out, int out_size) {
    const float* x     = (const float*)d_in[0];
    const float* fe_w  = (const float*)d_in[1];
    const float* fe_b  = (const float*)d_in[2];
    const float* s_w   = (const float*)d_in[3];
    const float* s_b   = (const float*)d_in[4];
    const float* e_w   = (const float*)d_in[5];
    const float* e_b   = (const float*)d_in[6];
    const float* g1_w  = (const float*)d_in[7];
    const float* g1_b  = (const float*)d_in[8];
    const float* bn1_g = (const float*)d_in[9];
    const float* bn1_b = (const float*)d_in[10];
    const float* ca1_w = (const float*)d_in[11];
    const float* ca1_b = (const float*)d_in[12];
    const float* ca2_w = (const float*)d_in[13];
    const float* ca2_b = (const float*)d_in[14];
    const float* g2_w  = (const float*)d_in[15];
    const float* g2_b  = (const float*)d_in[16];
    const float* bn2_g = (const float*)d_in[17];
    const float* bn2_b = (const float*)d_in[18];
    const float* g3_w  = (const float*)d_in[19];
    const float* g3_b  = (const float*)d_in[20];
    float* out = (float*)d_out;

    cudaFuncSetAttribute(feat_mma, cudaFuncAttributeMaxDynamicSharedMemorySize, F_SMEM);
    cudaFuncSetAttribute(out_mma,  cudaFuncAttributeMaxDynamicSharedMemorySize, O_SMEM);

    prep_kernel<<<48, 256>>>(fe_w, s_w, e_w);
    feat_mma<<<NB * 128, 256, F_SMEM>>>(x, fe_b, s_b, out);
    gate_kernel<<<1, 256>>>(g1_w, g1_b, bn1_g, bn1_b, ca1_w, ca1_b,
                            ca2_w, ca2_b, g2_w, g2_b, bn2_g, bn2_b, g3_w, g3_b);
    out_mma<<<NB * 128, 256, O_SMEM>>>(e_b, out);
}

// round 17
// speedup vs baseline: 1.0822x; 1.0822x over previous
#include <cuda_runtime.h>
#include <cuda_bf16.h>
#include <math.h>
#include <stdint.h>

#define HW 16384
#define NB 32

// ---------------- scratch (static device globals) ----------------
__device__ __align__(16) __nv_bfloat16 g_fh[(size_t)4096 * 8192];
__device__ __align__(16) __nv_bfloat16 g_fl[(size_t)4096 * 8192];
__device__ __align__(16) __nv_bfloat16 g_wh[10 * 4096];   // mats 0-7 experts, 8-9 shared; [o][c]
__device__ __align__(16) __nv_bfloat16 g_wl[10 * 4096];
__device__ __align__(16) __nv_bfloat16 g_fwh[4096];       // fe_w [o][c]
__device__ __align__(16) __nv_bfloat16 g_fwl[4096];
__device__ float g_gf[NB * 64];
__device__ int   g_tidx[NB * 2];
__device__ float g_tw[NB * 2];

__device__ __forceinline__ float rcp_approx(float v) {
    float r; asm("rcp.approx.f32 %0, %1;" : "=f"(r) : "f"(v)); return r;
}
__device__ __forceinline__ float ex2_approx(float v) {
    float r; asm("ex2.approx.f32 %0, %1;" : "=f"(r) : "f"(v)); return r;
}
// Branchless gelu: erf via Abramowitz-Stegun 7.1.26 (|err| <= 1.5e-7)
__device__ __forceinline__ float gelu_f(float x) {
    float a = fabsf(x) * 0.7071067811865476f;
    float t = rcp_approx(fmaf(0.3275911f, a, 1.0f));
    float ex = ex2_approx((-1.4426950408889634f * a) * a);
    float p = fmaf(1.061405429f, t, -1.453152027f);
    p = fmaf(p, t, 1.421413741f);
    p = fmaf(p, t, -0.284496736f);
    p = fmaf(p, t, 0.254829592f);
    float e = fmaf(-p * t, ex, 1.0f);
    float er = copysignf(e, x);
    float hx = 0.5f * x;
    return fmaf(hx, er, hx);
}
__device__ __forceinline__ void bsplit(float v, __nv_bfloat16& h, __nv_bfloat16& l) {
    h = __float2bfloat16(v);
    l = __float2bfloat16(v - __bfloat162float(h));
}
// Packed bf16x2 convert: word = {lo16 = bf16(vlo), hi16 = bf16(vhi)}, round-nearest
// (PTX operand order: cvt d, hi_src, lo_src — verified vs ptx_helpers CVT_BF16X2_F32)
__device__ __forceinline__ uint32_t cvt_bf2(float vlo, float vhi) {
    uint32_t r;
    asm("cvt.rn.bf16x2.f32 %0, %1, %2;" : "=r"(r) : "f"(vhi), "f"(vlo));
    return r;
}
// Split a pair: hi word + residual-lo word (bf16 = top half of f32 -> shifts)
__device__ __forceinline__ void bsplit2(float v0, float v1, uint32_t& wh, uint32_t& wl) {
    wh = cvt_bf2(v0, v1);
    float h0 = __uint_as_float(wh << 16);
    float h1 = __uint_as_float(wh & 0xffff0000u);
    wl = cvt_bf2(v0 - h0, v1 - h1);
}
__device__ __forceinline__ uint32_t smem_u32(const void* p) {
    uint32_t a;
    asm("{ .reg .u64 t; cvta.to.shared.u64 t, %1; cvt.u32.u64 %0, t; }" : "=r"(a) : "l"(p));
    return a;
}
__device__ __forceinline__ void ldsm4(uint32_t* r, uint32_t a) {
    asm volatile("ldmatrix.sync.aligned.m8n8.x4.shared.b16 {%0,%1,%2,%3}, [%4];"
                 : "=r"(r[0]), "=r"(r[1]), "=r"(r[2]), "=r"(r[3]) : "r"(a));
}
__device__ __forceinline__ void ldsm4t(uint32_t* r, uint32_t a) {
    asm volatile("ldmatrix.sync.aligned.m8n8.x4.trans.shared.b16 {%0,%1,%2,%3}, [%4];"
                 : "=r"(r[0]), "=r"(r[1]), "=r"(r[2]), "=r"(r[3]) : "r"(a));
}
__device__ __forceinline__ void mma16816(float* d, const uint32_t* a, const uint32_t* b) {
    asm volatile(
        "mma.sync.aligned.m16n8k16.row.col.f32.bf16.bf16.f32 "
        "{%0,%1,%2,%3}, {%4,%5,%6,%7}, {%8,%9}, {%0,%1,%2,%3};"
        : "+f"(d[0]), "+f"(d[1]), "+f"(d[2]), "+f"(d[3])
        : "r"(a[0]), "r"(a[1]), "r"(a[2]), "r"(a[3]), "r"(b[0]), "r"(b[1]));
}
__device__ __forceinline__ void cp16(uint32_t dst, const void* src) {
    asm volatile("cp.async.cg.shared.global [%0], [%1], 16;" :: "r"(dst), "l"(src));
}
#define CP_COMMIT_WAIT() \
    asm volatile("cp.async.commit_group;\n\tcp.async.wait_group 0;" ::: "memory")

#define AS_B 272   // A smem row stride bytes: [k=c rows][m=p cols], 136 bf16
#define BS_B 144   // B smem row stride bytes: [n rows][k cols], 72 bf16

// ---------------- prep: zero gf, bf16-split all weights ----------------
__global__ void prep_kernel(const float* __restrict__ fe_w,
                            const float* __restrict__ s_w,
                            const float* __restrict__ e_w) {
    int gt = blockIdx.x * blockDim.x + threadIdx.x;
    int stride = gridDim.x * blockDim.x;
    for (int i = gt; i < NB * 64; i += stride) g_gf[i] = 0.0f;
    for (int i = gt; i < 4096; i += stride) {
        __nv_bfloat16 h, l; bsplit(fe_w[i], h, l);
        g_fwh[i] = h; g_fwl[i] = l;
    }
    for (int i = gt; i < 10 * 4096; i += stride) {
        int m = i >> 12, r = i & 4095;
        float v = (m < 8) ? e_w[i] : s_w[(m - 8) * 4096 + r];
        __nv_bfloat16 h, l; bsplit(v, h, l);
        g_wh[i] = h; g_wl[i] = l;
    }
}

// ---------------- kernel 1: features (M=128 px, N=64, K=64), mma.sync 3-pass ----------------
#define F_AH 0
#define F_AL 17408
#define F_BH 34816
#define F_BL 44032
#define F_SMEM 53248
__global__ __launch_bounds__(256, 2) void feat_mma(const float* __restrict__ x,
                                                   const float* __restrict__ fe_b) {
    extern __shared__ char sm[];
    uint32_t sb = smem_u32(sm);
    int tid = threadIdx.x, wid = tid >> 5, lid = tid & 31;
    int b = blockIdx.x >> 7, t = blockIdx.x & 127;

    // stage A: x [c][p] (read-once, streaming) -> split bf16 smem [c][p], packed cvts
    const float* xb = x + (size_t)b * 64 * HW + (size_t)t * 128;
    #pragma unroll
    for (int it = 0; it < 8; it++) {
        int idx = tid + it * 256;          // 0..2047
        int p4 = idx & 31, c = idx >> 5;   // p chunk of 4, channel
        float4 v = __ldcs((const float4*)(xb + (size_t)c * HW + p4 * 4));
        uint32_t wh0, wl0, wh1, wl1;
        bsplit2(v.x, v.y, wh0, wl0);
        bsplit2(v.z, v.w, wh1, wl1);
        *(uint2*)(sm + F_AH + c * AS_B + p4 * 8) = make_uint2(wh0, wh1);
        *(uint2*)(sm + F_AL + c * AS_B + p4 * 8) = make_uint2(wl0, wl1);
    }
    // stage B: fe_w [o][c] bf16 planes, uint4 rows into stride-72
    for (int i = tid; i < 512; i += 256) {
        int o = i >> 3, ch = i & 7;
        *(uint4*)(sm + F_BH + o * BS_B + ch * 16) = ((const uint4*)g_fwh)[i];
        *(uint4*)(sm + F_BL + o * BS_B + ch * 16) = ((const uint4*)g_fwl)[i];
    }
    __syncthreads();

    int wm = wid & 3, wn = wid >> 2;      // 4 x 2 warp grid, tile 32x32
    int m0 = wm * 32, n0 = wn * 32;

    int asel = lid >> 3, akr = lid & 7;
    uint32_t aRow = (uint32_t)(((asel >> 1) * 8 + akr) * AS_B);
    uint32_t aCol = (uint32_t)((m0 + (asel & 1) * 8) * 2);
    int bsel = lid >> 3;
    uint32_t bRow = (uint32_t)(((bsel >> 1) * 8 + (lid & 7)) * BS_B);
    uint32_t bCol = (uint32_t)((bsel & 1) * 16);

    float acc[2][4][4];
    #pragma unroll
    for (int i = 0; i < 2; i++)
        #pragma unroll
        for (int j = 0; j < 4; j++)
            #pragma unroll
            for (int k = 0; k < 4; k++) acc[i][j][k] = 0.0f;

    // cache A-hi fragments (reused by passes 0 and 1)
    uint32_t afh[4][2][4];
    #pragma unroll
    for (int kk = 0; kk < 4; kk++) {
        uint32_t Ab = sb + F_AH + aRow + aCol + kk * 16 * AS_B;
        ldsm4t(afh[kk][0], Ab);
        ldsm4t(afh[kk][1], Ab + 32);
    }
    // passes 0 (A-hi x B-hi) and 1 (A-hi x B-lo)
    #pragma unroll
    for (int pb = 0; pb < 2; pb++) {
        uint32_t Bb = sb + (pb ? F_BL : F_BH) + bRow + bCol;
        #pragma unroll
        for (int kk = 0; kk < 4; kk++) {
            uint32_t bq0[4], bq1[4];
            ldsm4(bq0, Bb + n0 * BS_B + kk * 32);
            ldsm4(bq1, Bb + (n0 + 16) * BS_B + kk * 32);
            #pragma unroll
            for (int mt = 0; mt < 2; mt++) {
                mma16816(acc[mt][0], afh[kk][mt], &bq0[0]);
                mma16816(acc[mt][1], afh[kk][mt], &bq0[2]);
                mma16816(acc[mt][2], afh[kk][mt], &bq1[0]);
                mma16816(acc[mt][3], afh[kk][mt], &bq1[2]);
            }
        }
    }
    // pass 2 (A-lo x B-hi)
    {
        uint32_t Bb = sb + F_BH + bRow + bCol;
        #pragma unroll
        for (int kk = 0; kk < 4; kk++) {
            uint32_t afl[2][4], bq0[4], bq1[4];
            uint32_t Abl = sb + F_AL + aRow + aCol + kk * 16 * AS_B;
            ldsm4t(afl[0], Abl);
            ldsm4t(afl[1], Abl + 32);
            ldsm4(bq0, Bb + n0 * BS_B + kk * 32);
            ldsm4(bq1, Bb + (n0 + 16) * BS_B + kk * 32);
            #pragma unroll
            for (int mt = 0; mt < 2; mt++) {
                mma16816(acc[mt][0], afl[mt], &bq0[0]);
                mma16816(acc[mt][1], afl[mt], &bq0[2]);
                mma16816(acc[mt][2], afl[mt], &bq1[0]);
                mma16816(acc[mt][3], afl[mt], &bq1[2]);
            }
        }
    }
    __syncthreads();   // done reading A; reuse A region as bf16 staging [c][p]

    int r0 = lid >> 2, cq = (lid & 3) * 2;
    float colsum[8];
    #pragma unroll
    for (int j = 0; j < 8; j++) colsum[j] = 0.0f;

    #pragma unroll
    for (int mt = 0; mt < 2; mt++)
        #pragma unroll
        for (int nt = 0; nt < 4; nt++) {
            int c0 = n0 + nt * 8 + cq;
            float bi0 = __ldg(&fe_b[c0]), bi1 = __ldg(&fe_b[c0 + 1]);
            #pragma unroll
            for (int hr = 0; hr < 2; hr++) {
                int p = m0 + mt * 16 + r0 + hr * 8;
                float v0 = gelu_f(acc[mt][nt][hr * 2 + 0] + bi0);
                float v1 = gelu_f(acc[mt][nt][hr * 2 + 1] + bi1);
                colsum[nt * 2 + 0] += v0;
                colsum[nt * 2 + 1] += v1;
                uint32_t wh, wl;
                bsplit2(v0, v1, wh, wl);   // v0 -> c0 row, v1 -> c0+1 row
                *(unsigned short*)(sm + F_AH + c0 * AS_B + p * 2) = (unsigned short)(wh & 0xffffu);
                *(unsigned short*)(sm + F_AH + (c0 + 1) * AS_B + p * 2) = (unsigned short)(wh >> 16);
                *(unsigned short*)(sm + F_AL + c0 * AS_B + p * 2) = (unsigned short)(wl & 0xffffu);
                *(unsigned short*)(sm + F_AL + (c0 + 1) * AS_B + p * 2) = (unsigned short)(wl >> 16);
            }
        }
    #pragma unroll
    for (int off = 16; off >= 4; off >>= 1)
        #pragma unroll
        for (int j = 0; j < 8; j++)
            colsum[j] += __shfl_down_sync(0xffffffffu, colsum[j], off);
    if (lid < 4) {
        #pragma unroll
        for (int nt = 0; nt < 4; nt++) {
            atomicAdd(&g_gf[b * 64 + n0 + nt * 8 + cq + 0], colsum[nt * 2 + 0]);
            atomicAdd(&g_gf[b * 64 + n0 + nt * 8 + cq + 1], colsum[nt * 2 + 1]);
        }
    }
    __syncthreads();

    // staging -> gmem planes [c][128] (normal caching: out consumes these)
    uint4* dh = (uint4*)(g_fh + (size_t)blockIdx.x * 8192);
    uint4* dl = (uint4*)(g_fl + (size_t)blockIdx.x * 8192);
    for (int i = tid; i < 1024; i += 256) {
        int row = i >> 4, ch = i & 15;
        dh[i] = *(const uint4*)(sm + F_AH + row * AS_B + ch * 16);
        dl[i] = *(const uint4*)(sm + F_AL + row * AS_B + ch * 16);
    }
}

// ---------------- kernel 2: gating MLP (single block, fp32) ----------------
__global__ __launch_bounds__(256) void gate_kernel(
        const float* __restrict__ g1_w, const float* __restrict__ g1_b,
        const float* __restrict__ bn1_g, const float* __restrict__ bn1_b,
        const float* __restrict__ ca1_w, const float* __restrict__ ca1_b,
        const float* __restrict__ ca2_w, const float* __restrict__ ca2_b,
        const float* __restrict__ g2_w, const float* __restrict__ g2_b,
        const float* __restrict__ bn2_g, const float* __restrict__ bn2_b,
        const float* __restrict__ g3_w, const float* __restrict__ g3_b) {
    __shared__ float gf[32][64];
    __shared__ float h1[32][128];
    __shared__ float a1[32][8];
    __shared__ float hh[32][64];
    __shared__ float sc[32][8];

    int tid = threadIdx.x;
    const float bnscale = rsqrtf(1.0f + 1e-5f);
    const float inv_hw = 1.0f / 16384.0f;

    for (int i = tid; i < 2048; i += 256) gf[i >> 6][i & 63] = g_gf[i] * inv_hw;
    __syncthreads();

    for (int i = tid; i < 4096; i += 256) {
        int b = i >> 7, j = i & 127;
        float s = g1_b[j];
        #pragma unroll 8
        for (int h = 0; h < 64; h++) s += gf[b][h] * g1_w[j * 64 + h];
        s = s * (bn1_g[j] * bnscale) + bn1_b[j];
        h1[b][j] = gelu_f(s);
    }
    __syncthreads();
    {
        int b = tid >> 3, i = tid & 7;
        float s = ca1_b[i];
        #pragma unroll 8
        for (int h = 0; h < 128; h++) s += h1[b][h] * ca1_w[i * 128 + h];
        a1[b][i] = gelu_f(s);
    }
    __syncthreads();
    for (int i = tid; i < 4096; i += 256) {
        int b = i >> 7, j = i & 127;
        float s = ca2_b[j];
        #pragma unroll
        for (int k = 0; k < 8; k++) s += a1[b][k] * ca2_w[j * 8 + k];
        h1[b][j] *= 1.0f / (1.0f + expf(-2.0f * s));
    }
    __syncthreads();
    for (int i = tid; i < 2048; i += 256) {
        int b = i >> 6, j = i & 63;
        float s = g2_b[j];
        #pragma unroll 8
        for (int h = 0; h < 128; h++) s += h1[b][h] * g2_w[j * 128 + h];
        s = s * (bn2_g[j] * bnscale) + bn2_b[j];
        hh[b][j] = gelu_f(s);
    }
    __syncthreads();
    {
        int b = tid >> 3, e = tid & 7;
        float s = g3_b[e];
        #pragma unroll 8
        for (int h = 0; h < 64; h++) s += hh[b][h] * g3_w[e * 64 + h];
        sc[b][e] = s;
    }
    __syncthreads();
    if (tid < 32) {
        int b = tid;
        float v1 = -INFINITY; int i1 = 0;
        for (int e = 0; e < 8; e++) { float v = sc[b][e]; if (v > v1) { v1 = v; i1 = e; } }
        float v2 = -INFINITY; int i2 = 0;
        for (int e = 0; e < 8; e++) {
            if (e == i1) continue;
            float v = sc[b][e]; if (v > v2) { v2 = v; i2 = e; }
        }
        float w1 = 1.0f / (1.0f + expf((v2 - v1) * 0.5f));
        g_tidx[b * 2 + 0] = i1; g_tidx[b * 2 + 1] = i2;
        g_tw[b * 2 + 0] = w1;  g_tw[b * 2 + 1] = 1.0f - w1;
    }
}

// ---------------- kernel 3: experts (M=128 px, 4 mats serial, K=64, 3-pass) ----------------
// Reverse tile order (L2 reuse); cp.async staging; streaming final stores.
#define O_AH 0
#define O_AL 17408
#define O_B  34816     // + mat*18432 (hi), +9216 (lo)
#define O_BIAS 108544  // 256 floats
#define O_SMEM 109632
__global__ __launch_bounds__(256, 2) void out_mma(const float* __restrict__ s_b,
                                                  const float* __restrict__ e_b,
                                                  float* __restrict__ out) {
    extern __shared__ char sm[];
    uint32_t sb = smem_u32(sm);
    int tid = threadIdx.x, wid = tid >> 5, lid = tid & 31;
    int gt = 4095 - blockIdx.x;           // reverse tile order for L2 reuse
    int b = gt >> 7, t = gt & 127;

    int e0 = g_tidx[2 * b], e1 = g_tidx[2 * b + 1];
    float cfa[4] = {0.5f, 0.5f, g_tw[2 * b], g_tw[2 * b + 1]};

    // stage A: pre-split feature planes via cp.async
    {
        const uint4* ah = (const uint4*)(g_fh + (size_t)gt * 8192);
        const uint4* al = (const uint4*)(g_fl + (size_t)gt * 8192);
        for (int i = tid; i < 1024; i += 256) {
            int row = i >> 4, ch = i & 15;
            cp16(sb + O_AH + row * AS_B + ch * 16, ah + i);
            cp16(sb + O_AL + row * AS_B + ch * 16, al + i);
        }
    }
    // stage B: 4 mats (shared0, shared1, expert e0, expert e1) via cp.async
    {
        int mats[4] = {8, 9, e0, e1};
        #pragma unroll
        for (int q = 0; q < 4; q++) {
            const uint4* bh = (const uint4*)(g_wh + mats[q] * 4096);
            const uint4* bl = (const uint4*)(g_wl + mats[q] * 4096);
            uint32_t bo = sb + O_B + q * 18432;
            for (int i = tid; i < 512; i += 256) {
                int o = i >> 3, ch = i & 7;
                cp16(bo + o * BS_B + ch * 16, bh + i);
                cp16(bo + 9216 + o * BS_B + ch * 16, bl + i);
            }
        }
        int m = tid >> 6, o = tid & 63;
        float bv = (m < 2) ? s_b[m * 64 + o]
                           : e_b[((m == 2) ? e0 : e1) * 64 + o];
        *(float*)(sm + O_BIAS + tid * 4) = bv;
    }
    CP_COMMIT_WAIT();
    __syncthreads();

    int wm = wid & 3, wn = wid >> 2;   // 4m x 2n warps; warp tile 32px x 32cols
    int m0 = wm * 32, n0 = wn * 32;

    int asel = lid >> 3, akr = lid & 7;
    uint32_t aRow = (uint32_t)(((asel >> 1) * 8 + akr) * AS_B);
    uint32_t aCol = (uint32_t)((m0 + (asel & 1) * 8) * 2);
    int bsel = lid >> 3;
    uint32_t bRow = (uint32_t)(((bsel >> 1) * 8 + (lid & 7)) * BS_B);
    uint32_t bCol = (uint32_t)((bsel & 1) * 16);

    int rr = lid >> 2, cq = (lid & 3) * 2;
    const float* bias = (const float*)(sm + O_BIAS);

    // cache A-hi fragments across ALL mats (A is q-invariant; used by passes 0,1)
    uint32_t afh[4][2][4];
    #pragma unroll
    for (int kk = 0; kk < 4; kk++) {
        uint32_t Ab = sb + O_AH + aRow + aCol + kk * 16 * AS_B;
        ldsm4t(afh[kk][0], Ab);
        ldsm4t(afh[kk][1], Ab + 32);
    }

    float comb[2][4][4];
    #pragma unroll
    for (int i = 0; i < 2; i++)
        #pragma unroll
        for (int j = 0; j < 4; j++)
            #pragma unroll
            for (int k = 0; k < 4; k++) comb[i][j][k] = 0.0f;

    #pragma unroll
    for (int q = 0; q < 4; q++) {
        float acc[2][4][4];
        #pragma unroll
        for (int i = 0; i < 2; i++)
            #pragma unroll
            for (int j = 0; j < 4; j++)
                #pragma unroll
                for (int k = 0; k < 4; k++) acc[i][j][k] = 0.0f;

        uint32_t Bbase = sb + O_B + q * 18432 + bRow + bCol;
        // passes 0 (A-hi x B-hi) and 1 (A-hi x B-lo)
        #pragma unroll
        for (int pb = 0; pb < 2; pb++) {
            uint32_t Bb = Bbase + (pb ? 9216u : 0u);
            #pragma unroll
            for (int kk = 0; kk < 4; kk++) {
                uint32_t bq0[4], bq1[4];
                ldsm4(bq0, Bb + n0 * BS_B + kk * 32);
                ldsm4(bq1, Bb + (n0 + 16) * BS_B + kk * 32);
                #pragma unroll
                for (int mt = 0; mt < 2; mt++) {
                    mma16816(acc[mt][0], afh[kk][mt], &bq0[0]);
                    mma16816(acc[mt][1], afh[kk][mt], &bq0[2]);
                    mma16816(acc[mt][2], afh[kk][mt], &bq1[0]);
                    mma16816(acc[mt][3], afh[kk][mt], &bq1[2]);
                }
            }
        }
        // pass 2 (A-lo x B-hi)
        #pragma unroll
        for (int kk = 0; kk < 4; kk++) {
            uint32_t afl[2][4], bq0[4], bq1[4];
            uint32_t Abl = sb + O_AL + aRow + aCol + kk * 16 * AS_B;
            ldsm4t(afl[0], Abl);
            ldsm4t(afl[1], Abl + 32);
            ldsm4(bq0, Bbase + n0 * BS_B + kk * 32);
            ldsm4(bq1, Bbase + (n0 + 16) * BS_B + kk * 32);
            #pragma unroll
            for (int mt = 0; mt < 2; mt++) {
                mma16816(acc[mt][0], afl[mt], &bq0[0]);
                mma16816(acc[mt][1], afl[mt], &bq0[2]);
                mma16816(acc[mt][2], afl[mt], &bq1[0]);
                mma16816(acc[mt][3], afl[mt], &bq1[2]);
            }
        }
        // gelu + weighted combine (registers only)
        float cf = cfa[q];
        #pragma unroll
        for (int nt = 0; nt < 4; nt++) {
            int c0 = n0 + nt * 8 + cq;
            float bi0 = bias[q * 64 + c0], bi1 = bias[q * 64 + c0 + 1];
            #pragma unroll
            for (int mt = 0; mt < 2; mt++)
                #pragma unroll
                for (int hr = 0; hr < 2; hr++) {
                    comb[mt][nt][hr * 2 + 0] += cf * gelu_f(acc[mt][nt][hr * 2 + 0] + bi0);
                    comb[mt][nt][hr * 2 + 1] += cf * gelu_f(acc[mt][nt][hr * 2 + 1] + bi1);
                }
        }
    }

    // direct register -> global, streaming (never re-read)
    float* ob = out + (size_t)b * 64 * HW + (size_t)t * 128;
    #pragma unroll
    for (int nt = 0; nt < 4; nt++) {
        int c0 = n0 + nt * 8 + cq;
        float* row0 = ob + (size_t)c0 * HW;
        float* row1 = ob + (size_t)(c0 + 1) * HW;
        #pragma unroll
        for (int mt = 0; mt < 2; mt++)
            #pragma unroll
            for (int hr = 0; hr < 2; hr++) {
                int p = m0 + mt * 16 + rr + hr * 8;
                __stcs(&row0[p], comb[mt][nt][hr * 2 + 0]);
                __stcs(&row1[p], comb[mt][nt][hr * 2 + 1]);
            }
    }
}

// ---------------- launch ----------------
extern "C" void kernel_launch(void* const* d_in, const int* in_sizes, int n_in,
                              void* d_out, int out_size) {
    const float* x     = (const float*)d_in[0];
    const float* fe_w  = (const float*)d_in[1];
    const float* fe_b  = (const float*)d_in[2];
    const float* s_w   = (const float*)d_in[3];
    const float* s_b   = (const float*)d_in[4];
    const float* e_w   = (const float*)d_in[5];
    const float* e_b   = (const float*)d_in[6];
    const float* g1_w  = (const float*)d_in[7];
    const float* g1_b  = (const float*)d_in[8];
    const float* bn1_g = (const float*)d_in[9];
    const float* bn1_b = (const float*)d_in[10];
    const float* ca1_w = (const float*)d_in[11];
    const float* ca1_b = (const float*)d_in[12];
    const float* ca2_w = (const float*)d_in[13];
    const float* ca2_b = (const float*)d_in[14];
    const float* g2_w  = (const float*)d_in[15];
    const float* g2_b  = (const float*)d_in[16];
    const float* bn2_g = (const float*)d_in[17];
    const float* bn2_b = (const float*)d_in[18];
    const float* g3_w  = (const float*)d_in[19];
    const float* g3_b  = (const float*)d_in[20];
    float* out = (float*)d_out;

    cudaFuncSetAttribute(feat_mma, cudaFuncAttributeMaxDynamicSharedMemorySize, F_SMEM);
    cudaFuncSetAttribute(out_mma,  cudaFuncAttributeMaxDynamicSharedMemorySize, O_SMEM);

    prep_kernel<<<48, 256>>>(fe_w, s_w, e_w);
    feat_mma<<<NB * 128, 256, F_SMEM>>>(x, fe_b);
    gate_kernel<<<1, 256>>>(g1_w, g1_b, bn1_g, bn1_b, ca1_w, ca1_b,
                            ca2_w, ca2_b, g2_w, g2_b, bn2_g, bn2_b, g3_w, g3_b);
    out_mma<<<NB * 128, 256, O_SMEM>>>(s_b, e_b, out);
}